// round 7
// baseline (speedup 1.0000x reference)
#include <cuda_runtime.h>
#include <cuda_fp16.h>
#include <cstdint>
#include <cfloat>

// Problem constants
#define BATCH 256
#define CW    8192
#define NC    64
#define NS    4096
#define NE    128
#define BM    128            // batch rows per CTA
#define BN    64             // dict entries per chunk
#define NCH   (NS / BN)      // 64 chunks
#define KS    8              // k-steps of 16
#define NTH   256

#define EMBED_ELEMS (BATCH * CW)
#define XSPITCH 132          // padded fp32 x row (bank-conflict-free refine)

// ---- smem layout (bytes) ----
#define SM_XF   0            // [8 ks][128 r][4 tg] uint2 = 32768 (fp16 hi A frags)
#define SM_BF   32768        // 2 x [8 ks][64 n][4 tg] uint2 = 32768
#define SM_XS   65536        // [128][132] fp32 = 67584
#define SM_DSQ  133120       // [2][64] float = 512
#define SM_WMIN 133632       // [2][128] float = 1024
#define SM_WIDX 134656       // [2][128] int   = 1024
#define SM_TOTAL 135680

static __device__ __forceinline__ void mma_f16_f32(float4& c, uint32_t a0, uint32_t a1,
                                                   uint32_t a2, uint32_t a3,
                                                   uint32_t b0, uint32_t b1) {
    asm("mma.sync.aligned.m16n8k16.row.col.f32.f16.f16.f32 "
        "{%0,%1,%2,%3}, {%4,%5,%6,%7}, {%8,%9}, {%0,%1,%2,%3};"
        : "+f"(c.x), "+f"(c.y), "+f"(c.z), "+f"(c.w)
        : "r"(a0), "r"(a1), "r"(a2), "r"(a3), "r"(b0), "r"(b1));
}

static __device__ __forceinline__ uint32_t pack_h2(float f0, float f1) {
    __half2 h = __float22half2_rn(make_float2(f0, f1));
    return *(uint32_t*)&h;
}

// exact fp32 score = |d|^2 - 2 x.d  (x row from smem, dict row from gmem)
static __device__ __forceinline__ float exact_score(const float* __restrict__ dictc,
                                                    const float* __restrict__ xsrow,
                                                    int idx) {
    const float4* dp = (const float4*)(dictc + (size_t)idx * NE);
    const float4* xp = (const float4*)xsrow;
    float dot = 0.f, ds = 0.f;
    #pragma unroll 8
    for (int j = 0; j < 32; ++j) {
        float4 d4 = dp[j];
        float4 x4 = xp[j];
        dot = fmaf(d4.x, x4.x, dot); ds = fmaf(d4.x, d4.x, ds);
        dot = fmaf(d4.y, x4.y, dot); ds = fmaf(d4.y, d4.y, ds);
        dot = fmaf(d4.z, x4.z, dot); ds = fmaf(d4.z, d4.z, ds);
        dot = fmaf(d4.w, x4.w, dot); ds = fmaf(d4.w, d4.w, ds);
    }
    return fmaf(-2.f, dot, ds);
}

// ====== single fused kernel: approx hi*hi GEMM -> top2 candidates -> exact rescore
// ======                      + one-hot zeros + ones + embed gather
__global__ __launch_bounds__(NTH, 1)
void vq_fused(const float* __restrict__ x, const float* __restrict__ dict,
              float* __restrict__ out) {
    extern __shared__ char smem[];
    uint2* XF = (uint2*)(smem + SM_XF);
    uint2* BF = (uint2*)(smem + SM_BF);
    float* XS = (float*)(smem + SM_XS);
    float* dsq = (float*)(smem + SM_DSQ);
    float* wmin = (float*)(smem + SM_WMIN);
    int*   widx = (int*)(smem + SM_WIDX);

    const int tid  = threadIdx.x;
    const int wid  = tid >> 5;
    const int lane = tid & 31;
    const int gid  = lane >> 2;        // 0..7
    const int tg   = lane & 3;         // 0..3
    const int m0   = (wid & 3) * 32;   // warp M origin
    const int wn   = wid >> 2;         // 0..1
    const int n0   = wn * 32;          // warp N origin

    const int c  = blockIdx.x;
    const int b0 = blockIdx.y * BM;

    // ---- fill XS (fp32) + XF (fp16 hi fragments) ----
    {
        const int r = tid >> 1;
        const int half = tid & 1;
        const float* xr = x + (size_t)(b0 + r) * CW + (size_t)c * NE + half * 64;
        float4 xv[16];
        #pragma unroll
        for (int j = 0; j < 16; ++j) xv[j] = *(const float4*)(xr + j * 4);
        float* xsrow = XS + r * XSPITCH + half * 64;
        #pragma unroll
        for (int j = 0; j < 16; ++j) *(float4*)(xsrow + j * 4) = xv[j];
        const float* pf = (const float*)xv;
        #pragma unroll
        for (int ksl = 0; ksl < 4; ++ksl) {
            const int ks = half * 4 + ksl;
            #pragma unroll
            for (int t = 0; t < 4; ++t) {
                const int l0 = ksl * 16 + 2 * t;
                XF[ks * 512 + r * 4 + t] =
                    make_uint2(pack_h2(pf[l0], pf[l0 + 1]), pack_h2(pf[l0 + 8], pf[l0 + 9]));
            }
        }
    }

    // ---- per-thread state ----
    float4 ahh[2][4];
    #pragma unroll
    for (int mt = 0; mt < 2; ++mt)
        #pragma unroll
        for (int nt = 0; nt < 4; ++nt) ahh[mt][nt] = make_float4(0.f, 0.f, 0.f, 0.f);

    float b1[4], b2[4];
    int   x1[4], x2[4];
    #pragma unroll
    for (int i = 0; i < 4; ++i) { b1[i] = FLT_MAX; b2[i] = FLT_MAX; x1[i] = 0; x2[i] = 0; }

    // dict conversion role: 4 threads per dict row
    const int dn   = tid >> 2;
    const int tseg = tid & 3;
    const float* dbase = dict + (size_t)c * NS * NE + tseg * 32;

    // one-hot zero-fill role
    const int zr = tid >> 4;           // 0..15
    const int zc = (tid & 15) * 4;     // 0..60

    float4 pre[8];
    {   // prefetch chunk 0
        const float* src = dbase + (size_t)dn * NE;
        #pragma unroll
        for (int j = 0; j < 8; ++j) pre[j] = *(const float4*)(src + j * 4);
    }

    // convert chunk 0 into buffer 0
    {
        const float* pf = (const float*)pre;
        float ss = 0.f;
        #pragma unroll
        for (int i = 0; i < 32; ++i) ss = fmaf(pf[i], pf[i], ss);
        #pragma unroll
        for (int j = 0; j < 2; ++j) {
            const int ks = tseg * 2 + j;
            #pragma unroll
            for (int t = 0; t < 4; ++t) {
                const int l0 = j * 16 + 2 * t;
                BF[ks * 256 + dn * 4 + t] =
                    make_uint2(pack_h2(pf[l0], pf[l0 + 1]), pack_h2(pf[l0 + 8], pf[l0 + 9]));
            }
        }
        ss += __shfl_xor_sync(0xffffffffu, ss, 1);
        ss += __shfl_xor_sync(0xffffffffu, ss, 2);
        if (tseg == 0) dsq[dn] = ss;
    }
    __syncthreads();

    for (int s = 0; s < NCH; ++s) {
        const int p = s & 1;
        const uint2* BFp = BF + p * 2048;

        // ---- prefetch next chunk ----
        if (s + 1 < NCH) {
            const float* src = dbase + (size_t)((s + 1) * BN + dn) * NE;
            #pragma unroll
            for (int j = 0; j < 8; ++j) pre[j] = *(const float4*)(src + j * 4);
        }

        // ---- one-hot zero-fill: segment s of all 128 owned rows ----
        {
            const size_t seg = (size_t)EMBED_ELEMS + (size_t)s * BN + zc;
            #pragma unroll
            for (int pz = 0; pz < 8; ++pz) {
                const int r = pz * 16 + zr;
                float4* dst = (float4*)(out + seg + ((size_t)(b0 + r) * NC + c) * NS);
                __stwt(dst, make_float4(0.f, 0.f, 0.f, 0.f));
            }
        }

        // ---- mma phase: single hi*hi pass ----
        #pragma unroll 4
        for (int ks = 0; ks < KS; ++ks) {
            uint2 A0[2], A1[2], Bv[4];
            #pragma unroll
            for (int mt = 0; mt < 2; ++mt) {
                A0[mt] = XF[ks * 512 + (m0 + mt * 16 + gid) * 4 + tg];
                A1[mt] = XF[ks * 512 + (m0 + mt * 16 + 8 + gid) * 4 + tg];
            }
            #pragma unroll
            for (int nt = 0; nt < 4; ++nt)
                Bv[nt] = BFp[ks * 256 + (n0 + nt * 8 + gid) * 4 + tg];

            #pragma unroll
            for (int mt = 0; mt < 2; ++mt)
                #pragma unroll
                for (int nt = 0; nt < 4; ++nt)
                    mma_f16_f32(ahh[mt][nt], A0[mt].x, A1[mt].x, A0[mt].y, A1[mt].y,
                                Bv[nt].x, Bv[nt].y);
        }

        // ---- convert chunk s+1 into other buffer ----
        if (s + 1 < NCH) {
            const int q = (s + 1) & 1;
            uint2* BFq = BF + q * 2048;
            const float* pf = (const float*)pre;
            float ss = 0.f;
            #pragma unroll
            for (int i = 0; i < 32; ++i) ss = fmaf(pf[i], pf[i], ss);
            #pragma unroll
            for (int j = 0; j < 2; ++j) {
                const int ks = tseg * 2 + j;
                #pragma unroll
                for (int t = 0; t < 4; ++t) {
                    const int l0 = j * 16 + 2 * t;
                    BFq[ks * 256 + dn * 4 + t] =
                        make_uint2(pack_h2(pf[l0], pf[l0 + 1]), pack_h2(pf[l0 + 8], pf[l0 + 9]));
                }
            }
            ss += __shfl_xor_sync(0xffffffffu, ss, 1);
            ss += __shfl_xor_sync(0xffffffffu, ss, 2);
            if (tseg == 0) dsq[q * 64 + dn] = ss;
        }

        // ---- epilogue: approx scores -> top-2 per slot, reset accs ----
        const int sbase = s * BN;
        #pragma unroll
        for (int mt = 0; mt < 2; ++mt) {
            #pragma unroll
            for (int nt = 0; nt < 4; ++nt) {
                const int colb = n0 + nt * 8 + 2 * tg;
                const float d0 = dsq[p * 64 + colb];
                const float d1 = dsq[p * 64 + colb + 1];
                float4 hh = ahh[mt][nt];
                const int i0 = sbase + colb;
                #pragma unroll
                for (int rh = 0; rh < 2; ++rh) {      // row gid / gid+8
                    const int sl = mt * 2 + rh;
                    const float sA = fmaf(-2.f, rh ? hh.z : hh.x, d0);
                    const float sB = fmaf(-2.f, rh ? hh.w : hh.y, d1);
                    if (sA < b1[sl]) { b2[sl] = b1[sl]; x2[sl] = x1[sl]; b1[sl] = sA; x1[sl] = i0; }
                    else if (sA < b2[sl]) { b2[sl] = sA; x2[sl] = i0; }
                    if (sB < b1[sl]) { b2[sl] = b1[sl]; x2[sl] = x1[sl]; b1[sl] = sB; x1[sl] = i0 + 1; }
                    else if (sB < b2[sl]) { b2[sl] = sB; x2[sl] = i0 + 1; }
                }
                ahh[mt][nt] = make_float4(0.f, 0.f, 0.f, 0.f);
            }
        }
        __syncthreads();   // BF buffer handoff
    }

    // ---- exact rescore of the 2 candidates per slot, reduce per row ----
    const float* dictc = dict + (size_t)c * NS * NE;
    #pragma unroll
    for (int slot = 0; slot < 4; ++slot) {
        const int r = m0 + (slot >> 1) * 16 + (slot & 1) * 8 + gid;
        const float* xsrow = XS + r * XSPITCH;
        const int ia = x1[slot], ib = x2[slot];
        float ea = exact_score(dictc, xsrow, ia);
        float eb = exact_score(dictc, xsrow, ib);
        float v; int ix;
        if (ea < eb || (ea == eb && ia < ib)) { v = ea; ix = ia; }
        else { v = eb; ix = ib; }
        #pragma unroll
        for (int off = 1; off <= 2; off <<= 1) {
            float ov = __shfl_xor_sync(0xffffffffu, v, off);
            int   oi = __shfl_xor_sync(0xffffffffu, ix, off);
            if (ov < v || (ov == v && oi < ix)) { v = ov; ix = oi; }
        }
        if (tg == 0) {
            wmin[wn * 128 + r] = v;
            widx[wn * 128 + r] = ix;
        }
    }
    __syncthreads();

    // ---- final per-row winner: write the 1.0 + stash for gather ----
    if (tid < 128) {
        const float v0 = wmin[tid], v1 = wmin[128 + tid];
        const int   i0 = widx[tid], i1 = widx[128 + tid];
        int best = (v1 < v0 || (v1 == v0 && i1 < i0)) ? i1 : i0;
        out[(size_t)EMBED_ELEMS + ((size_t)(b0 + tid) * NC + c) * NS + best] = 1.0f;
        widx[tid] = best;
    }
    __syncthreads();

    // ---- gather nearest codewords into the embed region (2 threads / row) ----
    {
        const int r = tid >> 1;
        const int half = tid & 1;
        const int ix = widx[r];
        const float4* src = (const float4*)(dictc + (size_t)ix * NE) + half * 16;
        float4* dst = (float4*)(out + (size_t)(b0 + r) * CW + c * NE) + half * 16;
        #pragma unroll
        for (int j = 0; j < 16; ++j) __stwt(&dst[j], src[j]);
    }
}

extern "C" void kernel_launch(void* const* d_in, const int* in_sizes, int n_in,
                              void* d_out, int out_size) {
    const float* x    = (const float*)d_in[0];   // [256, 8192]
    const float* dict = (const float*)d_in[1];   // [64, 4096, 128]
    float* out = (float*)d_out;

    cudaFuncSetAttribute(vq_fused,
                         cudaFuncAttributeMaxDynamicSharedMemorySize, SM_TOTAL);

    vq_fused<<<dim3(NC, BATCH / BM), NTH, SM_TOTAL>>>(x, dict, out);
}

// round 8
// speedup vs baseline: 1.0377x; 1.0377x over previous
#include <cuda_runtime.h>
#include <cuda_fp16.h>
#include <cstdint>
#include <cfloat>

// Problem constants
#define BATCH 256
#define CW    8192
#define NC    64
#define NS    4096
#define NE    128
#define BM    128            // batch rows per CTA
#define BN    64             // dict entries per chunk
#define NCH   (NS / BN)      // 64 chunks
#define KS    8              // k-steps of 16
#define NTH   512

#define EMBED_ELEMS (BATCH * CW)
#define XSPITCH 132          // padded fp32 x row (bank-conflict-free refine)

// ---- smem layout (bytes) ----
#define SM_XF   0            // [8 ks][128 r][4 tg] uint2 = 32768 (fp16 hi A frags)
#define SM_BF   32768        // 2 x [8 ks][64 n][4 tg] uint2 = 32768
#define SM_XS   65536        // [128][132] fp32 = 67584
#define SM_DSQ  133120       // [2][64] float = 512
#define SM_WMIN 133632       // [4][128] float = 2048
#define SM_WIDX 135680       // [4][128] int   = 2048
#define SM_TOTAL 137728

static __device__ __forceinline__ void mma_f16_f32(float4& c, uint32_t a0, uint32_t a1,
                                                   uint32_t a2, uint32_t a3,
                                                   uint32_t b0, uint32_t b1) {
    asm("mma.sync.aligned.m16n8k16.row.col.f32.f16.f16.f32 "
        "{%0,%1,%2,%3}, {%4,%5,%6,%7}, {%8,%9}, {%0,%1,%2,%3};"
        : "+f"(c.x), "+f"(c.y), "+f"(c.z), "+f"(c.w)
        : "r"(a0), "r"(a1), "r"(a2), "r"(a3), "r"(b0), "r"(b1));
}

static __device__ __forceinline__ uint32_t pack_h2(float f0, float f1) {
    __half2 h = __float22half2_rn(make_float2(f0, f1));
    return *(uint32_t*)&h;
}

// exact fp32 score = |d|^2 - 2 x.d  (x row from smem, dict row from gmem/L2)
static __device__ __forceinline__ float exact_score(const float* __restrict__ dictc,
                                                    const float* __restrict__ xsrow,
                                                    int idx) {
    const float4* dp = (const float4*)(dictc + (size_t)idx * NE);
    const float4* xp = (const float4*)xsrow;
    float dot = 0.f, ds = 0.f;
    #pragma unroll 8
    for (int j = 0; j < 32; ++j) {
        float4 d4 = dp[j];
        float4 x4 = xp[j];
        dot = fmaf(d4.x, x4.x, dot); ds = fmaf(d4.x, d4.x, ds);
        dot = fmaf(d4.y, x4.y, dot); ds = fmaf(d4.y, d4.y, ds);
        dot = fmaf(d4.z, x4.z, dot); ds = fmaf(d4.z, d4.z, ds);
        dot = fmaf(d4.w, x4.w, dot); ds = fmaf(d4.w, d4.w, ds);
    }
    return fmaf(-2.f, dot, ds);
}

// ====== fused kernel (512 thr): approx hi*hi GEMM -> top2 -> exact rescore
// ======                         + one-hot zeros + ones + embed gather
__global__ __launch_bounds__(NTH, 1)
void vq_fused(const float* __restrict__ x, const float* __restrict__ dict,
              float* __restrict__ out) {
    extern __shared__ char smem[];
    uint2* XF = (uint2*)(smem + SM_XF);
    uint2* BF = (uint2*)(smem + SM_BF);
    float* XS = (float*)(smem + SM_XS);
    float* dsq = (float*)(smem + SM_DSQ);
    float* wmin = (float*)(smem + SM_WMIN);
    int*   widx = (int*)(smem + SM_WIDX);

    const int tid  = threadIdx.x;
    const int wid  = tid >> 5;
    const int lane = tid & 31;
    const int gid  = lane >> 2;        // 0..7
    const int tg   = lane & 3;         // 0..3
    const int m0   = (wid & 3) * 32;   // m-warp origin (4 m-warps)
    const int nw   = wid >> 2;         // 0..3 (4 n-warps)
    const int n0   = nw * 16;          // n-warp origin

    const int c  = blockIdx.x;
    const int b0 = blockIdx.y * BM;

    // ---- fill XS (fp32) + XF (fp16 hi fragments): 4 threads per row ----
    {
        const int r = tid >> 2;            // 0..127
        const int qr = tid & 3;            // 32-col quarter
        const float* xr = x + (size_t)(b0 + r) * CW + (size_t)c * NE + qr * 32;
        float4 xv[8];
        #pragma unroll
        for (int j = 0; j < 8; ++j) xv[j] = *(const float4*)(xr + j * 4);
        float* xsrow = XS + r * XSPITCH + qr * 32;
        #pragma unroll
        for (int j = 0; j < 8; ++j) *(float4*)(xsrow + j * 4) = xv[j];
        const float* pf = (const float*)xv;
        #pragma unroll
        for (int j = 0; j < 2; ++j) {
            const int ks = qr * 2 + j;
            #pragma unroll
            for (int t = 0; t < 4; ++t) {
                const int l0 = j * 16 + 2 * t;
                XF[ks * 512 + r * 4 + t] =
                    make_uint2(pack_h2(pf[l0], pf[l0 + 1]), pack_h2(pf[l0 + 8], pf[l0 + 9]));
            }
        }
    }

    // ---- per-thread state ----
    float4 acc[2][2];
    #pragma unroll
    for (int mt = 0; mt < 2; ++mt)
        #pragma unroll
        for (int nt = 0; nt < 2; ++nt) acc[mt][nt] = make_float4(0.f, 0.f, 0.f, 0.f);

    float b1[4], b2[4];
    int   x1[4], x2[4];
    #pragma unroll
    for (int i = 0; i < 4; ++i) { b1[i] = FLT_MAX; b2[i] = FLT_MAX; x1[i] = 0; x2[i] = 0; }

    // dict conversion role: 8 threads per dict row (16-col segment = one ks)
    const int dn   = tid >> 3;             // 0..63
    const int tseg = tid & 7;              // 0..7 == ks
    const float* dbase = dict + (size_t)c * NS * NE + tseg * 16;

    // one-hot zero-fill role: 2048 float4/chunk over 512 threads = 4 each
    const int zr = tid >> 4;               // 0..31
    const int zc = (tid & 15) * 4;         // 0..60

    float4 pre[4];
    {   // prefetch chunk 0 (16 floats per thread)
        const float* src = dbase + (size_t)dn * NE;
        #pragma unroll
        for (int j = 0; j < 4; ++j) pre[j] = *(const float4*)(src + j * 4);
    }

    // convert chunk 0 into buffer 0
    {
        const float* pf = (const float*)pre;
        float ss = 0.f;
        #pragma unroll
        for (int i = 0; i < 16; ++i) ss = fmaf(pf[i], pf[i], ss);
        #pragma unroll
        for (int t = 0; t < 4; ++t) {
            BF[tseg * 256 + dn * 4 + t] =
                make_uint2(pack_h2(pf[2 * t], pf[2 * t + 1]), pack_h2(pf[2 * t + 8], pf[2 * t + 9]));
        }
        ss += __shfl_xor_sync(0xffffffffu, ss, 1);
        ss += __shfl_xor_sync(0xffffffffu, ss, 2);
        ss += __shfl_xor_sync(0xffffffffu, ss, 4);
        if (tseg == 0) dsq[dn] = ss;
    }
    __syncthreads();

    for (int s = 0; s < NCH; ++s) {
        const int p = s & 1;
        const uint2* BFp = BF + p * 2048;

        // ---- prefetch next chunk ----
        if (s + 1 < NCH) {
            const float* src = dbase + (size_t)((s + 1) * BN + dn) * NE;
            #pragma unroll
            for (int j = 0; j < 4; ++j) pre[j] = *(const float4*)(src + j * 4);
        }

        // ---- one-hot zero-fill: segment s of all 128 owned rows ----
        {
            const size_t seg = (size_t)EMBED_ELEMS + (size_t)s * BN + zc;
            #pragma unroll
            for (int pz = 0; pz < 4; ++pz) {
                const int r = pz * 32 + zr;
                float4* dst = (float4*)(out + seg + ((size_t)(b0 + r) * NC + c) * NS);
                __stwt(dst, make_float4(0.f, 0.f, 0.f, 0.f));
            }
        }

        // ---- mma phase: 8 ks x (2m x 2n) single hi*hi pass ----
        #pragma unroll
        for (int ks = 0; ks < KS; ++ks) {
            uint2 A0[2], A1[2], Bv[2];
            #pragma unroll
            for (int mt = 0; mt < 2; ++mt) {
                A0[mt] = XF[ks * 512 + (m0 + mt * 16 + gid) * 4 + tg];
                A1[mt] = XF[ks * 512 + (m0 + mt * 16 + 8 + gid) * 4 + tg];
            }
            #pragma unroll
            for (int nt = 0; nt < 2; ++nt)
                Bv[nt] = BFp[ks * 256 + (n0 + nt * 8 + gid) * 4 + tg];

            #pragma unroll
            for (int mt = 0; mt < 2; ++mt)
                #pragma unroll
                for (int nt = 0; nt < 2; ++nt)
                    mma_f16_f32(acc[mt][nt], A0[mt].x, A1[mt].x, A0[mt].y, A1[mt].y,
                                Bv[nt].x, Bv[nt].y);
        }

        // ---- convert chunk s+1 into other buffer ----
        if (s + 1 < NCH) {
            const int q = (s + 1) & 1;
            uint2* BFq = BF + q * 2048;
            const float* pf = (const float*)pre;
            float ss = 0.f;
            #pragma unroll
            for (int i = 0; i < 16; ++i) ss = fmaf(pf[i], pf[i], ss);
            #pragma unroll
            for (int t = 0; t < 4; ++t) {
                BFq[tseg * 256 + dn * 4 + t] =
                    make_uint2(pack_h2(pf[2 * t], pf[2 * t + 1]),
                               pack_h2(pf[2 * t + 8], pf[2 * t + 9]));
            }
            ss += __shfl_xor_sync(0xffffffffu, ss, 1);
            ss += __shfl_xor_sync(0xffffffffu, ss, 2);
            ss += __shfl_xor_sync(0xffffffffu, ss, 4);
            if (tseg == 0) dsq[q * 64 + dn] = ss;
        }

        // ---- epilogue: approx scores -> top-2 per slot, reset accs ----
        const int sbase = s * BN;
        #pragma unroll
        for (int mt = 0; mt < 2; ++mt) {
            #pragma unroll
            for (int nt = 0; nt < 2; ++nt) {
                const int colb = n0 + nt * 8 + 2 * tg;
                const float d0 = dsq[p * 64 + colb];
                const float d1 = dsq[p * 64 + colb + 1];
                float4 hh = acc[mt][nt];
                const int i0 = sbase + colb;
                #pragma unroll
                for (int rh = 0; rh < 2; ++rh) {      // row gid / gid+8
                    const int sl = mt * 2 + rh;
                    const float sA = fmaf(-2.f, rh ? hh.z : hh.x, d0);
                    const float sB = fmaf(-2.f, rh ? hh.w : hh.y, d1);
                    if (sA < b1[sl]) { b2[sl] = b1[sl]; x2[sl] = x1[sl]; b1[sl] = sA; x1[sl] = i0; }
                    else if (sA < b2[sl]) { b2[sl] = sA; x2[sl] = i0; }
                    if (sB < b1[sl]) { b2[sl] = b1[sl]; x2[sl] = x1[sl]; b1[sl] = sB; x1[sl] = i0 + 1; }
                    else if (sB < b2[sl]) { b2[sl] = sB; x2[sl] = i0 + 1; }
                }
                acc[mt][nt] = make_float4(0.f, 0.f, 0.f, 0.f);
            }
        }
        __syncthreads();   // BF buffer handoff
    }

    // ---- exact rescore of the 2 candidates per slot, reduce per row ----
    const float* dictc = dict + (size_t)c * NS * NE;
    #pragma unroll
    for (int slot = 0; slot < 4; ++slot) {
        const int r = m0 + (slot >> 1) * 16 + (slot & 1) * 8 + gid;
        const float* xsrow = XS + r * XSPITCH;
        const int ia = x1[slot], ib = x2[slot];
        float ea = exact_score(dictc, xsrow, ia);
        float eb = exact_score(dictc, xsrow, ib);
        float v; int ix;
        if (ea < eb || (ea == eb && ia < ib)) { v = ea; ix = ia; }
        else { v = eb; ix = ib; }
        #pragma unroll
        for (int off = 1; off <= 2; off <<= 1) {
            float ov = __shfl_xor_sync(0xffffffffu, v, off);
            int   oi = __shfl_xor_sync(0xffffffffu, ix, off);
            if (ov < v || (ov == v && oi < ix)) { v = ov; ix = oi; }
        }
        if (tg == 0) {
            wmin[nw * 128 + r] = v;
            widx[nw * 128 + r] = ix;
        }
    }
    __syncthreads();

    // ---- final per-row winner across the 4 n-warps: 1.0 + stash ----
    if (tid < 128) {
        float v = wmin[tid];
        int  ix = widx[tid];
        #pragma unroll
        for (int k = 1; k < 4; ++k) {
            const float ov = wmin[k * 128 + tid];
            const int   oi = widx[k * 128 + tid];
            if (ov < v || (ov == v && oi < ix)) { v = ov; ix = oi; }
        }
        out[(size_t)EMBED_ELEMS + ((size_t)(b0 + tid) * NC + c) * NS + ix] = 1.0f;
        widx[tid] = ix;
    }
    __syncthreads();

    // ---- gather nearest codewords into the embed region (4 threads / row) ----
    {
        const int r = tid >> 2;
        const int qr = tid & 3;
        const int ix = widx[r];
        const float4* src = (const float4*)(dictc + (size_t)ix * NE) + qr * 8;
        float4* dst = (float4*)(out + (size_t)(b0 + r) * CW + c * NE) + qr * 8;
        #pragma unroll
        for (int j = 0; j < 8; ++j) __stwt(&dst[j], src[j]);
    }
}

extern "C" void kernel_launch(void* const* d_in, const int* in_sizes, int n_in,
                              void* d_out, int out_size) {
    const float* x    = (const float*)d_in[0];   // [256, 8192]
    const float* dict = (const float*)d_in[1];   // [64, 4096, 128]
    float* out = (float*)d_out;

    cudaFuncSetAttribute(vq_fused,
                         cudaFuncAttributeMaxDynamicSharedMemorySize, SM_TOTAL);

    vq_fused<<<dim3(NC, BATCH / BM), NTH, SM_TOTAL>>>(x, dict, out);
}